// round 1
// baseline (speedup 1.0000x reference)
#include <cuda_runtime.h>
#include <cuda_bf16.h>

// Problem constants
#define BB   8
#define QQ   1024
#define KK   1024
#define EMBED 2048
#define DOWN  512
#define HH    16
#define DHD   32    // down head dim
#define DH    128   // value head dim

// Scratch (device globals: allocation-free rule)
__device__ float g_q[BB * QQ * DOWN];     // 16 MB
__device__ float g_k[BB * KK * DOWN];     // 16 MB
__device__ float g_v[BB * KK * EMBED];    // 64 MB

// ---------------- packed f32x2 helpers ----------------
__device__ __forceinline__ unsigned long long pk2(float x, float y) {
    unsigned long long r;
    asm("mov.b64 %0, {%1, %2};" : "=l"(r) : "f"(x), "f"(y));
    return r;
}
__device__ __forceinline__ float2 upk2(unsigned long long v) {
    float x, y;
    asm("mov.b64 {%0, %1}, %2;" : "=f"(x), "=f"(y) : "l"(v));
    return make_float2(x, y);
}
__device__ __forceinline__ void fma2(unsigned long long& d,
                                     unsigned long long a,
                                     unsigned long long b) {
    asm("fma.rn.f32x2 %0, %1, %2, %0;" : "+l"(d) : "l"(a), "l"(b));
}

// ---------------- GEMM: C[M,N] = A[M,K] @ W[N,K]^T + bias[N] ----------------
// BM=BN=128, BK=16, 256 threads, 8x8 microtile, f32x2 packed FMAs.
__global__ void __launch_bounds__(256)
gemm_nt_bias(const float* __restrict__ A, const float* __restrict__ W,
             const float* __restrict__ bias, float* __restrict__ C,
             int M, int N, int K) {
    __shared__ float As[16][132];
    __shared__ float Bs[16][132];
    const int tid = threadIdx.x;
    const int ty = tid >> 4, tx = tid & 15;
    const int m0 = blockIdx.y * 128, n0 = blockIdx.x * 128;

    unsigned long long acc[8][4];
#pragma unroll
    for (int i = 0; i < 8; i++)
#pragma unroll
        for (int j = 0; j < 4; j++) acc[i][j] = 0ull;

    for (int kt = 0; kt < K; kt += 16) {
#pragma unroll
        for (int l = 0; l < 2; l++) {
            int i = tid + l * 256;          // 0..511
            int row = i >> 2;               // 0..127
            int kq = (i & 3) << 2;          // 0,4,8,12
            float4 a4 = *(const float4*)(A + (size_t)(m0 + row) * K + kt + kq);
            As[kq + 0][row] = a4.x; As[kq + 1][row] = a4.y;
            As[kq + 2][row] = a4.z; As[kq + 3][row] = a4.w;
            float4 b4 = *(const float4*)(W + (size_t)(n0 + row) * K + kt + kq);
            Bs[kq + 0][row] = b4.x; Bs[kq + 1][row] = b4.y;
            Bs[kq + 2][row] = b4.z; Bs[kq + 3][row] = b4.w;
        }
        __syncthreads();
#pragma unroll
        for (int k = 0; k < 16; k++) {
            float4 a0 = *(const float4*)&As[k][ty * 8];
            float4 a1 = *(const float4*)&As[k][ty * 8 + 4];
            float4 b0 = *(const float4*)&Bs[k][tx * 8];
            float4 b1 = *(const float4*)&Bs[k][tx * 8 + 4];
            unsigned long long bp[4] = {pk2(b0.x, b0.y), pk2(b0.z, b0.w),
                                        pk2(b1.x, b1.y), pk2(b1.z, b1.w)};
            float av[8] = {a0.x, a0.y, a0.z, a0.w, a1.x, a1.y, a1.z, a1.w};
#pragma unroll
            for (int i = 0; i < 8; i++) {
                unsigned long long ap = pk2(av[i], av[i]);
                fma2(acc[i][0], ap, bp[0]);
                fma2(acc[i][1], ap, bp[1]);
                fma2(acc[i][2], ap, bp[2]);
                fma2(acc[i][3], ap, bp[3]);
            }
        }
        __syncthreads();
    }

    float4 bb0 = *(const float4*)(bias + n0 + tx * 8);
    float4 bb1 = *(const float4*)(bias + n0 + tx * 8 + 4);
#pragma unroll
    for (int i = 0; i < 8; i++) {
        float2 c0 = upk2(acc[i][0]), c1 = upk2(acc[i][1]);
        float2 c2 = upk2(acc[i][2]), c3 = upk2(acc[i][3]);
        float4 o0 = make_float4(c0.x + bb0.x, c0.y + bb0.y, c1.x + bb0.z, c1.y + bb0.w);
        float4 o1 = make_float4(c2.x + bb1.x, c2.y + bb1.y, c3.x + bb1.z, c3.y + bb1.w);
        float* crow = C + (size_t)(m0 + ty * 8 + i) * N + n0 + tx * 8;
        *(float4*)crow = o0;
        *(float4*)(crow + 4) = o1;
    }
}

// ---------------- fused attention ----------------
// grid (Q/128, H, B), 256 threads. K-head cached in SMEM (128KB).
// sweep1: online max/log-sum-exp per q row. sweep2 (16 chunks of 64 k):
// recompute scores -> probabilities -> write weights (coalesced) + P@V accum.
__global__ void __launch_bounds__(256)
attn_kernel(const float* __restrict__ qp, const float* __restrict__ kp,
            const float* __restrict__ vp, const float* __restrict__ mask,
            float* __restrict__ outO, float* __restrict__ outW) {
    const int b = blockIdx.z, h = blockIdx.y;
    const int qb0 = blockIdx.x * 128;
    const int tid = threadIdx.x;

    extern __shared__ float sm[];
    float* Kh   = sm;              // 1024*32      = 32768
    float* P    = Kh + 32768;      // 128*65       =  8320
    float* Vc   = P + 8320;        // 64*128       =  8192
    float* rowC = Vc + 8192;       // 128
    float* redM = rowC + 128;      // 256
    float* redS = redM + 256;      // 256

    // load K head [1024,32] into smem
    {
        const float* kb = kp + (size_t)b * KK * DOWN + h * DHD;
        for (int i = tid; i < 1024 * 8; i += 256) {
            int row = i >> 3, c = (i & 7) << 2;
            *(float4*)(Kh + row * 32 + c) =
                *(const float4*)(kb + (size_t)row * DOWN + c);
        }
    }

    const int r = tid & 127;        // q row within tile
    const int part = tid >> 7;      // k half
    // Q row into registers as 16 f32x2 pairs
    unsigned long long q2[16];
    {
        const float* qrow = qp + (size_t)(b * QQ + qb0 + r) * DOWN + h * DHD;
#pragma unroll
        for (int i = 0; i < 16; i++) q2[i] = pk2(qrow[2 * i], qrow[2 * i + 1]);
    }
    __syncthreads();

    const float scale = 0.1767766952966369f; // 1/sqrt(32)
    const float* mrow = mask + (size_t)b * QQ * KK + (size_t)(qb0 + r) * KK;

    // ---- sweep 1: online max & sum-exp over this thread's k-half ----
    float m = -1e30f, s = 0.f;
    {
        const int k0 = part * 512;
        for (int k = k0; k < k0 + 512; k++) {
            const float* kr = Kh + k * 32;
            unsigned long long a = 0ull;
#pragma unroll
            for (int i = 0; i < 16; i++)
                fma2(a, q2[i], *(const unsigned long long*)(kr + 2 * i));
            float2 af = upk2(a);
            float dot = af.x + af.y;
            float mv = mrow[k];
            float sv = fmaf(dot, scale, (mv == 0.f) ? -10000.f : mv);
            if (sv <= m) {
                s += __expf(sv - m);
            } else {
                s = fmaf(s, __expf(m - sv), 1.f);
                m = sv;
            }
        }
    }
    redM[tid] = m;
    redS[tid] = s;
    __syncthreads();
    if (tid < 128) {
        float m0 = redM[tid], m1 = redM[tid + 128];
        float s0 = redS[tid], s1 = redS[tid + 128];
        float M = fmaxf(m0, m1);
        float S = s0 * __expf(m0 - M) + s1 * __expf(m1 - M);
        rowC[tid] = M + __logf(S);   // w = exp(sv - C)
    }
    __syncthreads();
    const float myC = rowC[r];

    // ---- sweep 2 ----
    const int ty = tid >> 4, tx = tid & 15;
    unsigned long long oacc[8][4];
#pragma unroll
    for (int i = 0; i < 8; i++)
#pragma unroll
        for (int j = 0; j < 4; j++) oacc[i][j] = 0ull;

    for (int cc = 0; cc < 16; cc++) {
        const int kb2 = cc * 64;
        __syncthreads();   // previous chunk's P/Vc fully consumed

        // phase a: recompute scores -> probabilities into P[q][kk] (stride 65)
        {
            const int kk0 = part * 32;
            for (int kk = kk0; kk < kk0 + 32; kk++) {
                int k = kb2 + kk;
                const float* kr = Kh + k * 32;
                unsigned long long a = 0ull;
#pragma unroll
                for (int i = 0; i < 16; i++)
                    fma2(a, q2[i], *(const unsigned long long*)(kr + 2 * i));
                float2 af = upk2(a);
                float dot = af.x + af.y;
                float mv = mrow[k];
                float sv = fmaf(dot, scale, (mv == 0.f) ? -10000.f : mv);
                P[r * 65 + kk] = __expf(sv - myC);
            }
        }
        // load V chunk [64,128]
        for (int i = tid; i < 64 * 32; i += 256) {
            int row = i >> 5, c = (i & 31) << 2;
            *(float4*)(Vc + row * 128 + c) =
                *(const float4*)(vp + (size_t)(b * KK + kb2 + row) * EMBED + h * DH + c);
        }
        __syncthreads();

        // phase b: write attention weights (coalesced along k)
        {
            float* wbase = outW + ((size_t)((b * HH + h) * QQ + qb0)) * KK + kb2;
            for (int i = tid; i < 128 * 64; i += 256) {
                int q = i >> 6, kk = i & 63;
                wbase[(size_t)q * KK + kk] = P[q * 65 + kk];
            }
        }

        // phase c: O += P_chunk @ V_chunk  (8x8 microtile, f32x2)
        for (int kk = 0; kk < 64; kk++) {
            float4 v0 = *(const float4*)(Vc + kk * 128 + tx * 8);
            float4 v1 = *(const float4*)(Vc + kk * 128 + tx * 8 + 4);
            unsigned long long vb_[4] = {pk2(v0.x, v0.y), pk2(v0.z, v0.w),
                                         pk2(v1.x, v1.y), pk2(v1.z, v1.w)};
#pragma unroll
            for (int i = 0; i < 8; i++) {
                float pa = P[(ty * 8 + i) * 65 + kk];
                unsigned long long pp = pk2(pa, pa);
                fma2(oacc[i][0], pp, vb_[0]);
                fma2(oacc[i][1], pp, vb_[1]);
                fma2(oacc[i][2], pp, vb_[2]);
                fma2(oacc[i][3], pp, vb_[3]);
            }
        }
    }

    // write O tile
#pragma unroll
    for (int i = 0; i < 8; i++) {
        float2 c0 = upk2(oacc[i][0]), c1 = upk2(oacc[i][1]);
        float2 c2 = upk2(oacc[i][2]), c3 = upk2(oacc[i][3]);
        float* orow = outO + (size_t)(b * QQ + qb0 + ty * 8 + i) * EMBED + h * DH + tx * 8;
        *(float4*)orow = make_float4(c0.x, c0.y, c1.x, c1.y);
        *(float4*)(orow + 4) = make_float4(c2.x, c2.y, c3.x, c3.y);
    }
}

// ---------------- launch ----------------
extern "C" void kernel_launch(void* const* d_in, const int* in_sizes, int n_in,
                              void* d_out, int out_size) {
    const float* query = (const float*)d_in[0];
    const float* key   = (const float*)d_in[1];
    const float* value = (const float*)d_in[2];
    const float* amask = (const float*)d_in[3];
    const float* qW = (const float*)d_in[4];
    const float* qb = (const float*)d_in[5];
    const float* kW = (const float*)d_in[6];
    const float* kb = (const float*)d_in[7];
    const float* vW = (const float*)d_in[8];
    const float* vb = (const float*)d_in[9];
    (void)in_sizes; (void)n_in; (void)out_size;

    float* outO = (float*)d_out;                             // [B,Q,EMBED]
    float* outW = outO + (size_t)BB * QQ * EMBED;            // [B,H,Q,K]

    float *pq, *pk_, *pv;
    cudaGetSymbolAddress((void**)&pq, g_q);
    cudaGetSymbolAddress((void**)&pk_, g_k);
    cudaGetSymbolAddress((void**)&pv, g_v);

    // projections
    {
        dim3 gq(DOWN / 128, (BB * QQ) / 128);
        gemm_nt_bias<<<gq, 256>>>(query, qW, qb, pq, BB * QQ, DOWN, DOWN);
        gemm_nt_bias<<<gq, 256>>>(key, kW, kb, pk_, BB * KK, DOWN, DOWN);
        dim3 gv(EMBED / 128, (BB * KK) / 128);
        gemm_nt_bias<<<gv, 256>>>(value, vW, vb, pv, BB * KK, EMBED, EMBED);
    }

    // fused attention
    {
        const int smem = (32768 + 8320 + 8192 + 128 + 256 + 256) * 4; // 199,680 B
        cudaFuncSetAttribute(attn_kernel,
                             cudaFuncAttributeMaxDynamicSharedMemorySize, smem);
        dim3 ga(QQ / 128, HH, BB);
        attn_kernel<<<ga, 256, smem>>>(pq, pk_, pv, amask, outO, outW);
    }
}

// round 2
// speedup vs baseline: 1.2374x; 1.2374x over previous
#include <cuda_runtime.h>
#include <cuda_bf16.h>

// Problem constants
#define BB   8
#define QQ   1024
#define KK   1024
#define EMBED 2048
#define DOWN  512
#define HH    16
#define DHD   32    // down head dim
#define DH    128   // value head dim

typedef unsigned long long ull;

// Scratch (device globals: allocation-free rule)
__device__ float g_q[BB * QQ * DOWN];     // 16 MB
__device__ float g_k[BB * KK * DOWN];     // 16 MB
__device__ float g_v[BB * KK * EMBED];    // 64 MB

// ---------------- packed f32x2 helpers ----------------
__device__ __forceinline__ ull pk2(float x, float y) {
    ull r;
    asm("mov.b64 %0, {%1, %2};" : "=l"(r) : "f"(x), "f"(y));
    return r;
}
__device__ __forceinline__ float2 upk2(ull v) {
    float x, y;
    asm("mov.b64 {%0, %1}, %2;" : "=f"(x), "=f"(y) : "l"(v));
    return make_float2(x, y);
}
__device__ __forceinline__ void fma2(ull& d, ull a, ull b) {
    asm("fma.rn.f32x2 %0, %1, %2, %0;" : "+l"(d) : "l"(a), "l"(b));
}

// ---------------- GEMM: C[M,N] = A[M,K] @ W[N,K]^T + bias[N] ----------------
__global__ void __launch_bounds__(256)
gemm_nt_bias(const float* __restrict__ A, const float* __restrict__ W,
             const float* __restrict__ bias, float* __restrict__ C,
             int M, int N, int K) {
    __shared__ float As[16][132];
    __shared__ float Bs[16][132];
    const int tid = threadIdx.x;
    const int ty = tid >> 4, tx = tid & 15;
    const int m0 = blockIdx.y * 128, n0 = blockIdx.x * 128;

    ull acc[8][4];
#pragma unroll
    for (int i = 0; i < 8; i++)
#pragma unroll
        for (int j = 0; j < 4; j++) acc[i][j] = 0ull;

    for (int kt = 0; kt < K; kt += 16) {
#pragma unroll
        for (int l = 0; l < 2; l++) {
            int i = tid + l * 256;
            int row = i >> 2;
            int kq = (i & 3) << 2;
            float4 a4 = *(const float4*)(A + (size_t)(m0 + row) * K + kt + kq);
            As[kq + 0][row] = a4.x; As[kq + 1][row] = a4.y;
            As[kq + 2][row] = a4.z; As[kq + 3][row] = a4.w;
            float4 b4 = *(const float4*)(W + (size_t)(n0 + row) * K + kt + kq);
            Bs[kq + 0][row] = b4.x; Bs[kq + 1][row] = b4.y;
            Bs[kq + 2][row] = b4.z; Bs[kq + 3][row] = b4.w;
        }
        __syncthreads();
#pragma unroll
        for (int k = 0; k < 16; k++) {
            float4 a0 = *(const float4*)&As[k][ty * 8];
            float4 a1 = *(const float4*)&As[k][ty * 8 + 4];
            float4 b0 = *(const float4*)&Bs[k][tx * 8];
            float4 b1 = *(const float4*)&Bs[k][tx * 8 + 4];
            ull bp[4] = {pk2(b0.x, b0.y), pk2(b0.z, b0.w),
                         pk2(b1.x, b1.y), pk2(b1.z, b1.w)};
            float av[8] = {a0.x, a0.y, a0.z, a0.w, a1.x, a1.y, a1.z, a1.w};
#pragma unroll
            for (int i = 0; i < 8; i++) {
                ull ap = pk2(av[i], av[i]);
                fma2(acc[i][0], ap, bp[0]);
                fma2(acc[i][1], ap, bp[1]);
                fma2(acc[i][2], ap, bp[2]);
                fma2(acc[i][3], ap, bp[3]);
            }
        }
        __syncthreads();
    }

    float4 bb0 = *(const float4*)(bias + n0 + tx * 8);
    float4 bb1 = *(const float4*)(bias + n0 + tx * 8 + 4);
#pragma unroll
    for (int i = 0; i < 8; i++) {
        float2 c0 = upk2(acc[i][0]), c1 = upk2(acc[i][1]);
        float2 c2 = upk2(acc[i][2]), c3 = upk2(acc[i][3]);
        float4 o0 = make_float4(c0.x + bb0.x, c0.y + bb0.y, c1.x + bb0.z, c1.y + bb0.w);
        float4 o1 = make_float4(c2.x + bb1.x, c2.y + bb1.y, c3.x + bb1.z, c3.y + bb1.w);
        float* crow = C + (size_t)(m0 + ty * 8 + i) * N + n0 + tx * 8;
        *(float4*)crow = o0;
        *(float4*)(crow + 4) = o1;
    }
}

// ---------------- fused attention (microtiled, swizzled) ----------------
// grid (Q/128, H, B), 256 threads, 1 CTA/SM (215KB smem).
// Kh: swizzled K head [1024,32]; Qs: Q tile [128,32].
// S microtile: (ty,tx)=16x16 threads, each 8q x 4k, fma2 paired along d.
// PV microtile: warp<->16 q rows, lane<->4 d cols, kk unrolled x4.
__global__ void __launch_bounds__(256)
attn_kernel(const float* __restrict__ qp, const float* __restrict__ kp,
            const float* __restrict__ vp, const float* __restrict__ mask,
            float* __restrict__ outO, float* __restrict__ outW) {
    const int b = blockIdx.z, h = blockIdx.y;
    const int qb0 = blockIdx.x * 128;
    const int tid = threadIdx.x;

    extern __shared__ float sm[];
    float* Kh   = sm;              // 1024*32 (swizzled)     = 32768 f
    float* Qs   = Kh + 32768;      // 128*32                 =  4096 f
    float* P    = Qs + 4096;       // 128*68                 =  8704 f
    float* Vc   = P + 8704;        // 64*128                 =  8192 f
    float* rowC = Vc + 8192;       // 128 f

    // ---- load K head (swizzled) + Q tile ----
    {
        const float* kb_ = kp + (size_t)b * KK * DOWN + h * DHD;
        for (int i = tid; i < 1024 * 8; i += 256) {
            int row = i >> 3, c = i & 7;
            float4 v = *(const float4*)(kb_ + (size_t)row * DOWN + c * 4);
            int cs = c ^ ((row >> 2) & 7);
            *(float4*)(Kh + row * 32 + cs * 4) = v;
        }
        const float* qb_ = qp + (size_t)(b * QQ + qb0) * DOWN + h * DHD;
        for (int i = tid; i < 128 * 8; i += 256) {
            int row = i >> 3, c = i & 7;
            *(float4*)(Qs + row * 32 + c * 4) =
                *(const float4*)(qb_ + (size_t)row * DOWN + c * 4);
        }
    }
    __syncthreads();

    const int ty = tid >> 4, tx = tid & 15;
    const float scale = 0.1767766952966369f; // 1/sqrt(32)
    const float* mbase = mask + (size_t)b * QQ * KK + (size_t)qb0 * KK;

    // ================= sweep 1: per-thread online (m,s), shfl-reduce at end =================
    float m_[8], s_[8];
#pragma unroll
    for (int i = 0; i < 8; i++) { m_[i] = -1e30f; s_[i] = 0.f; }

    for (int cc = 0; cc < 16; cc++) {
        const int kb2 = cc * 64;
        // S microtile
        ull acc[8][4];
#pragma unroll
        for (int i = 0; i < 8; i++)
#pragma unroll
            for (int j = 0; j < 4; j++) acc[i][j] = 0ull;
#pragma unroll
        for (int d4 = 0; d4 < 8; d4++) {
            ull kpr[4][2];
#pragma unroll
            for (int j = 0; j < 4; j++) {
                int k = kb2 + tx * 4 + j;
                int cs = d4 ^ ((k >> 2) & 7);
                const ull* kc = (const ull*)(Kh + k * 32 + cs * 4);
                kpr[j][0] = kc[0]; kpr[j][1] = kc[1];
            }
#pragma unroll
            for (int i = 0; i < 8; i++) {
                const ull* qc = (const ull*)(Qs + (ty * 8 + i) * 32 + d4 * 4);
                ull q0 = qc[0], q1 = qc[1];
#pragma unroll
                for (int j = 0; j < 4; j++) {
                    fma2(acc[i][j], q0, kpr[j][0]);
                    fma2(acc[i][j], q1, kpr[j][1]);
                }
            }
        }
#pragma unroll
        for (int i = 0; i < 8; i++) {
            float4 mv = *(const float4*)(mbase + (size_t)(ty * 8 + i) * KK + kb2 + tx * 4);
            float t0 = (mv.x == 0.f) ? -10000.f : mv.x;
            float t1 = (mv.y == 0.f) ? -10000.f : mv.y;
            float t2 = (mv.z == 0.f) ? -10000.f : mv.z;
            float t3 = (mv.w == 0.f) ? -10000.f : mv.w;
            float2 a0 = upk2(acc[i][0]), a1 = upk2(acc[i][1]);
            float2 a2 = upk2(acc[i][2]), a3 = upk2(acc[i][3]);
            float s0 = fmaf(a0.x + a0.y, scale, t0);
            float s1 = fmaf(a1.x + a1.y, scale, t1);
            float s2 = fmaf(a2.x + a2.y, scale, t2);
            float s3 = fmaf(a3.x + a3.y, scale, t3);
            float cm = fmaxf(fmaxf(s0, s1), fmaxf(s2, s3));
            float nm = fmaxf(m_[i], cm);
            float corr = __expf(m_[i] - nm);
            float es = __expf(s0 - nm) + __expf(s1 - nm) +
                       __expf(s2 - nm) + __expf(s3 - nm);
            s_[i] = fmaf(s_[i], corr, es);
            m_[i] = nm;
        }
    }
    // cross-tx reduce (16 lanes within half-warp)
#pragma unroll
    for (int off = 1; off < 16; off <<= 1) {
#pragma unroll
        for (int i = 0; i < 8; i++) {
            float om = __shfl_xor_sync(0xffffffffu, m_[i], off);
            float os = __shfl_xor_sync(0xffffffffu, s_[i], off);
            float nm = fmaxf(m_[i], om);
            s_[i] = s_[i] * __expf(m_[i] - nm) + os * __expf(om - nm);
            m_[i] = nm;
        }
    }
    if (tx == 0) {
#pragma unroll
        for (int i = 0; i < 8; i++)
            rowC[ty * 8 + i] = m_[i] + __logf(s_[i]);
    }
    __syncthreads();

    // hoisted per-row constants
    float C_[8];
#pragma unroll
    for (int i = 0; i < 8; i++) C_[i] = rowC[ty * 8 + i];

    // PV mapping
    const int wq = tid >> 5;        // warp -> 16 q rows
    const int lane = tid & 31;      // lane -> 4 d cols
    const int dcol = lane * 4;
    ull oacc[16][2];
#pragma unroll
    for (int i = 0; i < 16; i++) { oacc[i][0] = 0ull; oacc[i][1] = 0ull; }

    // ================= sweep 2: recompute S -> weights + PV =================
    for (int cc = 0; cc < 16; cc++) {
        const int kb2 = cc * 64;
        ull acc[8][4];
#pragma unroll
        for (int i = 0; i < 8; i++)
#pragma unroll
            for (int j = 0; j < 4; j++) acc[i][j] = 0ull;
#pragma unroll
        for (int d4 = 0; d4 < 8; d4++) {
            ull kpr[4][2];
#pragma unroll
            for (int j = 0; j < 4; j++) {
                int k = kb2 + tx * 4 + j;
                int cs = d4 ^ ((k >> 2) & 7);
                const ull* kc = (const ull*)(Kh + k * 32 + cs * 4);
                kpr[j][0] = kc[0]; kpr[j][1] = kc[1];
            }
#pragma unroll
            for (int i = 0; i < 8; i++) {
                const ull* qc = (const ull*)(Qs + (ty * 8 + i) * 32 + d4 * 4);
                ull q0 = qc[0], q1 = qc[1];
#pragma unroll
                for (int j = 0; j < 4; j++) {
                    fma2(acc[i][j], q0, kpr[j][0]);
                    fma2(acc[i][j], q1, kpr[j][1]);
                }
            }
        }
        float4 w4[8];
#pragma unroll
        for (int i = 0; i < 8; i++) {
            float4 mv = *(const float4*)(mbase + (size_t)(ty * 8 + i) * KK + kb2 + tx * 4);
            float t0 = (mv.x == 0.f) ? -10000.f : mv.x;
            float t1 = (mv.y == 0.f) ? -10000.f : mv.y;
            float t2 = (mv.z == 0.f) ? -10000.f : mv.z;
            float t3 = (mv.w == 0.f) ? -10000.f : mv.w;
            float2 a0 = upk2(acc[i][0]), a1 = upk2(acc[i][1]);
            float2 a2 = upk2(acc[i][2]), a3 = upk2(acc[i][3]);
            w4[i].x = __expf(fmaf(a0.x + a0.y, scale, t0) - C_[i]);
            w4[i].y = __expf(fmaf(a1.x + a1.y, scale, t1) - C_[i]);
            w4[i].z = __expf(fmaf(a2.x + a2.y, scale, t2) - C_[i]);
            w4[i].w = __expf(fmaf(a3.x + a3.y, scale, t3) - C_[i]);
        }
        // weights -> global (coalesced, no smem involved)
        {
            float* wbase = outW + ((size_t)((b * HH + h) * QQ + qb0 + ty * 8)) * KK + kb2 + tx * 4;
#pragma unroll
            for (int i = 0; i < 8; i++)
                *(float4*)(wbase + (size_t)i * KK) = w4[i];
        }
        __syncthreads();   // prior PV done with P, Vc
        // stage P
#pragma unroll
        for (int i = 0; i < 8; i++)
            *(float4*)(P + (ty * 8 + i) * 68 + tx * 4) = w4[i];
        // load V chunk [64,128]
        for (int i2 = tid; i2 < 64 * 32; i2 += 256) {
            int row = i2 >> 5, c = (i2 & 31) << 2;
            *(float4*)(Vc + row * 128 + c) =
                *(const float4*)(vp + (size_t)(b * KK + kb2 + row) * EMBED + h * DH + c);
        }
        __syncthreads();

        // PV: O += P_chunk @ V_chunk
#pragma unroll
        for (int kk = 0; kk < 64; kk += 4) {
            ull v_[4][2];
#pragma unroll
            for (int t = 0; t < 4; t++) {
                const ull* pv = (const ull*)(Vc + (kk + t) * 128 + dcol);
                v_[t][0] = pv[0]; v_[t][1] = pv[1];
            }
#pragma unroll
            for (int i = 0; i < 16; i++) {
                float4 p4 = *(const float4*)(P + (wq * 16 + i) * 68 + kk);
                ull p0 = pk2(p4.x, p4.x), p1 = pk2(p4.y, p4.y);
                ull p2 = pk2(p4.z, p4.z), p3 = pk2(p4.w, p4.w);
                fma2(oacc[i][0], p0, v_[0][0]); fma2(oacc[i][1], p0, v_[0][1]);
                fma2(oacc[i][0], p1, v_[1][0]); fma2(oacc[i][1], p1, v_[1][1]);
                fma2(oacc[i][0], p2, v_[2][0]); fma2(oacc[i][1], p2, v_[2][1]);
                fma2(oacc[i][0], p3, v_[3][0]); fma2(oacc[i][1], p3, v_[3][1]);
            }
        }
    }

    // write O
#pragma unroll
    for (int i = 0; i < 16; i++) {
        float2 a = upk2(oacc[i][0]);
        float2 c = upk2(oacc[i][1]);
        float* orow = outO + (size_t)(b * QQ + qb0 + wq * 16 + i) * EMBED + h * DH + dcol;
        *(float4*)orow = make_float4(a.x, a.y, c.x, c.y);
    }
}

// ---------------- launch ----------------
extern "C" void kernel_launch(void* const* d_in, const int* in_sizes, int n_in,
                              void* d_out, int out_size) {
    const float* query = (const float*)d_in[0];
    const float* key   = (const float*)d_in[1];
    const float* value = (const float*)d_in[2];
    const float* amask = (const float*)d_in[3];
    const float* qW = (const float*)d_in[4];
    const float* qb = (const float*)d_in[5];
    const float* kW = (const float*)d_in[6];
    const float* kb = (const float*)d_in[7];
    const float* vW = (const float*)d_in[8];
    const float* vb = (const float*)d_in[9];
    (void)in_sizes; (void)n_in; (void)out_size;

    float* outO = (float*)d_out;                             // [B,Q,EMBED]
    float* outW = outO + (size_t)BB * QQ * EMBED;            // [B,H,Q,K]

    float *pq, *pk_, *pv;
    cudaGetSymbolAddress((void**)&pq, g_q);
    cudaGetSymbolAddress((void**)&pk_, g_k);
    cudaGetSymbolAddress((void**)&pv, g_v);

    {
        dim3 gq(DOWN / 128, (BB * QQ) / 128);
        gemm_nt_bias<<<gq, 256>>>(query, qW, qb, pq, BB * QQ, DOWN, DOWN);
        gemm_nt_bias<<<gq, 256>>>(key, kW, kb, pk_, BB * KK, DOWN, DOWN);
        dim3 gv(EMBED / 128, (BB * KK) / 128);
        gemm_nt_bias<<<gv, 256>>>(value, vW, vb, pv, BB * KK, EMBED, EMBED);
    }

    {
        const int smem = (32768 + 4096 + 8704 + 8192 + 128) * 4; // 215,552 B
        cudaFuncSetAttribute(attn_kernel,
                             cudaFuncAttributeMaxDynamicSharedMemorySize, smem);
        dim3 ga(QQ / 128, HH, BB);
        attn_kernel<<<ga, 256, smem>>>(pq, pk_, pv, amask, outO, outW);
    }
}

// round 4
// speedup vs baseline: 1.7598x; 1.4221x over previous
#include <cuda_runtime.h>
#include <cuda_bf16.h>
#include <cstdint>

// Problem constants
#define BB   8
#define QQ   1024
#define KK   1024
#define EMBED 2048
#define DOWN  512
#define HH    16
#define DHD   32    // down head dim
#define DH    128   // value head dim

typedef unsigned long long ull;

// Scratch (device globals: allocation-free rule)
__device__ float g_q[BB * QQ * DOWN];     // 16 MB
__device__ float g_k[BB * KK * DOWN];     // 16 MB
__device__ float g_v[BB * KK * EMBED];    // 64 MB

// ---------------- packed f32x2 helpers ----------------
__device__ __forceinline__ ull pk2(float x, float y) {
    ull r;
    asm("mov.b64 %0, {%1, %2};" : "=l"(r) : "f"(x), "f"(y));
    return r;
}
__device__ __forceinline__ float2 upk2(ull v) {
    float x, y;
    asm("mov.b64 {%0, %1}, %2;" : "=f"(x), "=f"(y) : "l"(v));
    return make_float2(x, y);
}
__device__ __forceinline__ void fma2(ull& d, ull a, ull b) {
    asm("fma.rn.f32x2 %0, %1, %2, %0;" : "+l"(d) : "l"(a), "l"(b));
}

// ---------------- mma.sync helpers (non-'a' PTX, works on sm_103) ----------------
__device__ __forceinline__ uint32_t smem_u32(const void* p) {
    uint32_t a;
    asm("{ .reg .u64 t; cvta.to.shared.u64 t, %1; cvt.u32.u64 %0, t; }"
        : "=r"(a) : "l"(p));
    return a;
}
__device__ __forceinline__ void ldmx4(uint32_t* r, uint32_t addr) {
    asm volatile("ldmatrix.sync.aligned.m8n8.x4.shared.b16 {%0,%1,%2,%3}, [%4];"
                 : "=r"(r[0]), "=r"(r[1]), "=r"(r[2]), "=r"(r[3]) : "r"(addr));
}
__device__ __forceinline__ void mma16816(float* d, const uint32_t* a, const uint32_t* b) {
    asm volatile(
        "mma.sync.aligned.m16n8k16.row.col.f32.bf16.bf16.f32 "
        "{%0,%1,%2,%3}, {%4,%5,%6,%7}, {%8,%9}, {%0,%1,%2,%3};"
        : "+f"(d[0]), "+f"(d[1]), "+f"(d[2]), "+f"(d[3])
        : "r"(a[0]), "r"(a[1]), "r"(a[2]), "r"(a[3]), "r"(b[0]), "r"(b[1]));
}
// pack two floats to bf16x2 (x0 -> low half / lower address)
__device__ __forceinline__ uint32_t bfpack(float x0, float x1) {
    uint32_t r;
    asm("cvt.rn.bf16x2.f32 %0, %1, %2;" : "=r"(r) : "f"(x1), "f"(x0));
    return r;
}

// ---------------- HMMA GEMM: C[M,N] = A[M,K] @ W[N,K]^T + bias ----------------
// 128x128 block, 8 warps (2x4), warp tile 64x32, K-chunk 32, split-bf16 x3.
// Smem tiles padded to 80B rows (40 bf16): conflict-free ldmatrix, no swizzle.
#define GS_A_HI 0u
#define GS_A_LO 10240u
#define GS_B_HI 20480u
#define GS_B_LO 30720u
#define GS_BYTES 40960u

__global__ void __launch_bounds__(256, 2)
gemm_mma(const float* __restrict__ A, const float* __restrict__ W,
         const float* __restrict__ bias, float* __restrict__ C,
         int M, int N, int K) {
    extern __shared__ char smem[];
    const uint32_t sb = smem_u32(smem);
    const int tid = threadIdx.x;
    const int warp = tid >> 5, lane = tid & 31;
    const int wm = warp >> 2, wn = warp & 3;
    const int warp_row = wm * 64, warp_col = wn * 32;
    const int m0 = blockIdx.y * 128, n0 = blockIdx.x * 128;

    float acc[4][4][4];
#pragma unroll
    for (int i = 0; i < 4; i++)
#pragma unroll
        for (int j = 0; j < 4; j++)
#pragma unroll
            for (int t = 0; t < 4; t++) acc[i][j][t] = 0.f;

    // ldmatrix lane addresses (byte offsets within a tile)
    // A (m16k16 x4): row = lane&15, +16B if lane>=16
    const uint32_t a_lane_off = (uint32_t)((lane & 15) * 80 + (lane >> 4) * 16);
    // B (two n8k16 tiles): lanes 0-7: n0-7 k0 | 8-15: n0-7 k8 | 16-23: n8-15 k0 | 24-31: n8-15 k8
    const uint32_t b_lane_off = (uint32_t)(((lane >> 4) * 8 + (lane & 7)) * 80 + ((lane >> 3) & 1) * 16);

    for (int kt = 0; kt < K; kt += 32) {
        __syncthreads();   // previous iteration's frags consumed
        // ---- fill smem: convert fp32 -> bf16 hi/lo ----
        const float* Ab = A + (size_t)m0 * K + kt;
        const float* Wb = W + (size_t)n0 * K + kt;
#pragma unroll
        for (int l = 0; l < 4; l++) {
            int i = tid + l * 256;          // 0..1023
            int r = i >> 3, c4 = i & 7;
            uint32_t off = (uint32_t)(r * 80 + c4 * 8);

            float4 a4 = *(const float4*)(Ab + (size_t)r * K + c4 * 4);
            float hx = __bfloat162float(__float2bfloat16_rn(a4.x));
            float hy = __bfloat162float(__float2bfloat16_rn(a4.y));
            float hz = __bfloat162float(__float2bfloat16_rn(a4.z));
            float hw = __bfloat162float(__float2bfloat16_rn(a4.w));
            *(uint2*)(smem + GS_A_HI + off) = make_uint2(bfpack(hx, hy), bfpack(hz, hw));
            *(uint2*)(smem + GS_A_LO + off) = make_uint2(bfpack(a4.x - hx, a4.y - hy),
                                                         bfpack(a4.z - hz, a4.w - hw));

            float4 w4 = *(const float4*)(Wb + (size_t)r * K + c4 * 4);
            hx = __bfloat162float(__float2bfloat16_rn(w4.x));
            hy = __bfloat162float(__float2bfloat16_rn(w4.y));
            hz = __bfloat162float(__float2bfloat16_rn(w4.z));
            hw = __bfloat162float(__float2bfloat16_rn(w4.w));
            *(uint2*)(smem + GS_B_HI + off) = make_uint2(bfpack(hx, hy), bfpack(hz, hw));
            *(uint2*)(smem + GS_B_LO + off) = make_uint2(bfpack(w4.x - hx, w4.y - hy),
                                                         bfpack(w4.z - hz, w4.w - hw));
        }
        __syncthreads();

        // ---- compute: 2 k16 steps x 3 products ----
#pragma unroll
        for (int kc = 0; kc < 2; kc++) {
            const uint32_t kco = (uint32_t)(kc * 32);
            uint32_t afrag[4][4], bfrag[2][4];

            // hi * hi
#pragma unroll
            for (int mt = 0; mt < 4; mt++)
                ldmx4(afrag[mt], sb + GS_A_HI + (uint32_t)((warp_row + mt * 16) * 80) + kco + a_lane_off);
#pragma unroll
            for (int np = 0; np < 2; np++)
                ldmx4(bfrag[np], sb + GS_B_HI + (uint32_t)((warp_col + np * 16) * 80) + kco + b_lane_off);
#pragma unroll
            for (int mt = 0; mt < 4; mt++)
#pragma unroll
                for (int nt = 0; nt < 4; nt++)
                    mma16816(acc[mt][nt], afrag[mt], &bfrag[nt >> 1][(nt & 1) * 2]);

            // lo * hi (B_hi still live)
#pragma unroll
            for (int mt = 0; mt < 4; mt++)
                ldmx4(afrag[mt], sb + GS_A_LO + (uint32_t)((warp_row + mt * 16) * 80) + kco + a_lane_off);
#pragma unroll
            for (int mt = 0; mt < 4; mt++)
#pragma unroll
                for (int nt = 0; nt < 4; nt++)
                    mma16816(acc[mt][nt], afrag[mt], &bfrag[nt >> 1][(nt & 1) * 2]);

            // hi * lo (reload A_hi, load B_lo)
#pragma unroll
            for (int mt = 0; mt < 4; mt++)
                ldmx4(afrag[mt], sb + GS_A_HI + (uint32_t)((warp_row + mt * 16) * 80) + kco + a_lane_off);
#pragma unroll
            for (int np = 0; np < 2; np++)
                ldmx4(bfrag[np], sb + GS_B_LO + (uint32_t)((warp_col + np * 16) * 80) + kco + b_lane_off);
#pragma unroll
            for (int mt = 0; mt < 4; mt++)
#pragma unroll
                for (int nt = 0; nt < 4; nt++)
                    mma16816(acc[mt][nt], afrag[mt], &bfrag[nt >> 1][(nt & 1) * 2]);
        }
    }

    // ---- epilogue: add bias, store fp32 ----
    const int lr = lane >> 2, lc = (lane & 3) * 2;
#pragma unroll
    for (int mt = 0; mt < 4; mt++) {
#pragma unroll
        for (int nt = 0; nt < 4; nt++) {
            int col = n0 + warp_col + nt * 8 + lc;
            float b0 = bias[col], b1 = bias[col + 1];
            int row0 = m0 + warp_row + mt * 16 + lr;
            float2 v0 = make_float2(acc[mt][nt][0] + b0, acc[mt][nt][1] + b1);
            float2 v1 = make_float2(acc[mt][nt][2] + b0, acc[mt][nt][3] + b1);
            *(float2*)(C + (size_t)row0 * N + col) = v0;
            *(float2*)(C + (size_t)(row0 + 8) * N + col) = v1;
        }
    }
}

// ---------------- fused attention (unchanged, known-good) ----------------
__global__ void __launch_bounds__(256)
attn_kernel(const float* __restrict__ qp, const float* __restrict__ kp,
            const float* __restrict__ vp, const float* __restrict__ mask,
            float* __restrict__ outO, float* __restrict__ outW) {
    const int b = blockIdx.z, h = blockIdx.y;
    const int qb0 = blockIdx.x * 128;
    const int tid = threadIdx.x;

    extern __shared__ float sm[];
    float* Kh   = sm;              // 1024*32 (swizzled)
    float* Qs   = Kh + 32768;      // 128*32
    float* P    = Qs + 4096;       // 128*68
    float* Vc   = P + 8704;        // 64*128
    float* rowC = Vc + 8192;       // 128

    {
        const float* kb_ = kp + (size_t)b * KK * DOWN + h * DHD;
        for (int i = tid; i < 1024 * 8; i += 256) {
            int row = i >> 3, c = i & 7;
            float4 v = *(const float4*)(kb_ + (size_t)row * DOWN + c * 4);
            int cs = c ^ ((row >> 2) & 7);
            *(float4*)(Kh + row * 32 + cs * 4) = v;
        }
        const float* qb_ = qp + (size_t)(b * QQ + qb0) * DOWN + h * DHD;
        for (int i = tid; i < 128 * 8; i += 256) {
            int row = i >> 3, c = i & 7;
            *(float4*)(Qs + row * 32 + c * 4) =
                *(const float4*)(qb_ + (size_t)row * DOWN + c * 4);
        }
    }
    __syncthreads();

    const int ty = tid >> 4, tx = tid & 15;
    const float scale = 0.1767766952966369f;
    const float* mbase = mask + (size_t)b * QQ * KK + (size_t)qb0 * KK;

    float m_[8], s_[8];
#pragma unroll
    for (int i = 0; i < 8; i++) { m_[i] = -1e30f; s_[i] = 0.f; }

    for (int cc = 0; cc < 16; cc++) {
        const int kb2 = cc * 64;
        ull acc[8][4];
#pragma unroll
        for (int i = 0; i < 8; i++)
#pragma unroll
            for (int j = 0; j < 4; j++) acc[i][j] = 0ull;
#pragma unroll
        for (int d4 = 0; d4 < 8; d4++) {
            ull kpr[4][2];
#pragma unroll
            for (int j = 0; j < 4; j++) {
                int k = kb2 + tx * 4 + j;
                int cs = d4 ^ ((k >> 2) & 7);
                const ull* kc = (const ull*)(Kh + k * 32 + cs * 4);
                kpr[j][0] = kc[0]; kpr[j][1] = kc[1];
            }
#pragma unroll
            for (int i = 0; i < 8; i++) {
                const ull* qc = (const ull*)(Qs + (ty * 8 + i) * 32 + d4 * 4);
                ull q0 = qc[0], q1 = qc[1];
#pragma unroll
                for (int j = 0; j < 4; j++) {
                    fma2(acc[i][j], q0, kpr[j][0]);
                    fma2(acc[i][j], q1, kpr[j][1]);
                }
            }
        }
#pragma unroll
        for (int i = 0; i < 8; i++) {
            float4 mv = *(const float4*)(mbase + (size_t)(ty * 8 + i) * KK + kb2 + tx * 4);
            float t0 = (mv.x == 0.f) ? -10000.f : mv.x;
            float t1 = (mv.y == 0.f) ? -10000.f : mv.y;
            float t2 = (mv.z == 0.f) ? -10000.f : mv.z;
            float t3 = (mv.w == 0.f) ? -10000.f : mv.w;
            float2 a0 = upk2(acc[i][0]), a1 = upk2(acc[i][1]);
            float2 a2 = upk2(acc[i][2]), a3 = upk2(acc[i][3]);
            float s0 = fmaf(a0.x + a0.y, scale, t0);
            float s1 = fmaf(a1.x + a1.y, scale, t1);
            float s2 = fmaf(a2.x + a2.y, scale, t2);
            float s3 = fmaf(a3.x + a3.y, scale, t3);
            float cm = fmaxf(fmaxf(s0, s1), fmaxf(s2, s3));
            float nm = fmaxf(m_[i], cm);
            float corr = __expf(m_[i] - nm);
            float es = __expf(s0 - nm) + __expf(s1 - nm) +
                       __expf(s2 - nm) + __expf(s3 - nm);
            s_[i] = fmaf(s_[i], corr, es);
            m_[i] = nm;
        }
    }
#pragma unroll
    for (int off = 1; off < 16; off <<= 1) {
#pragma unroll
        for (int i = 0; i < 8; i++) {
            float om = __shfl_xor_sync(0xffffffffu, m_[i], off);
            float os = __shfl_xor_sync(0xffffffffu, s_[i], off);
            float nm = fmaxf(m_[i], om);
            s_[i] = s_[i] * __expf(m_[i] - nm) + os * __expf(om - nm);
            m_[i] = nm;
        }
    }
    if (tx == 0) {
#pragma unroll
        for (int i = 0; i < 8; i++)
            rowC[ty * 8 + i] = m_[i] + __logf(s_[i]);
    }
    __syncthreads();

    float C_[8];
#pragma unroll
    for (int i = 0; i < 8; i++) C_[i] = rowC[ty * 8 + i];

    const int wq = tid >> 5;
    const int lane = tid & 31;
    const int dcol = lane * 4;
    ull oacc[16][2];
#pragma unroll
    for (int i = 0; i < 16; i++) { oacc[i][0] = 0ull; oacc[i][1] = 0ull; }

    for (int cc = 0; cc < 16; cc++) {
        const int kb2 = cc * 64;
        ull acc[8][4];
#pragma unroll
        for (int i = 0; i < 8; i++)
#pragma unroll
            for (int j = 0; j < 4; j++) acc[i][j] = 0ull;
#pragma unroll
        for (int d4 = 0; d4 < 8; d4++) {
            ull kpr[4][2];
#pragma unroll
            for (int j = 0; j < 4; j++) {
                int k = kb2 + tx * 4 + j;
                int cs = d4 ^ ((k >> 2) & 7);
                const ull* kc = (const ull*)(Kh + k * 32 + cs * 4);
                kpr[j][0] = kc[0]; kpr[j][1] = kc[1];
            }
#pragma unroll
            for (int i = 0; i < 8; i++) {
                const ull* qc = (const ull*)(Qs + (ty * 8 + i) * 32 + d4 * 4);
                ull q0 = qc[0], q1 = qc[1];
#pragma unroll
                for (int j = 0; j < 4; j++) {
                    fma2(acc[i][j], q0, kpr[j][0]);
                    fma2(acc[i][j], q1, kpr[j][1]);
                }
            }
        }
        float4 w4[8];
#pragma unroll
        for (int i = 0; i < 8; i++) {
            float4 mv = *(const float4*)(mbase + (size_t)(ty * 8 + i) * KK + kb2 + tx * 4);
            float t0 = (mv.x == 0.f) ? -10000.f : mv.x;
            float t1 = (mv.y == 0.f) ? -10000.f : mv.y;
            float t2 = (mv.z == 0.f) ? -10000.f : mv.z;
            float t3 = (mv.w == 0.f) ? -10000.f : mv.w;
            float2 a0 = upk2(acc[i][0]), a1 = upk2(acc[i][1]);
            float2 a2 = upk2(acc[i][2]), a3 = upk2(acc[i][3]);
            w4[i].x = __expf(fmaf(a0.x + a0.y, scale, t0) - C_[i]);
            w4[i].y = __expf(fmaf(a1.x + a1.y, scale, t1) - C_[i]);
            w4[i].z = __expf(fmaf(a2.x + a2.y, scale, t2) - C_[i]);
            w4[i].w = __expf(fmaf(a3.x + a3.y, scale, t3) - C_[i]);
        }
        {
            float* wbase = outW + ((size_t)((b * HH + h) * QQ + qb0 + ty * 8)) * KK + kb2 + tx * 4;
#pragma unroll
            for (int i = 0; i < 8; i++)
                *(float4*)(wbase + (size_t)i * KK) = w4[i];
        }
        __syncthreads();
#pragma unroll
        for (int i = 0; i < 8; i++)
            *(float4*)(P + (ty * 8 + i) * 68 + tx * 4) = w4[i];
        for (int i2 = tid; i2 < 64 * 32; i2 += 256) {
            int row = i2 >> 5, c = (i2 & 31) << 2;
            *(float4*)(Vc + row * 128 + c) =
                *(const float4*)(vp + (size_t)(b * KK + kb2 + row) * EMBED + h * DH + c);
        }
        __syncthreads();

#pragma unroll
        for (int kk = 0; kk < 64; kk += 4) {
            ull v_[4][2];
#pragma unroll
            for (int t = 0; t < 4; t++) {
                const ull* pv = (const ull*)(Vc + (kk + t) * 128 + dcol);
                v_[t][0] = pv[0]; v_[t][1] = pv[1];
            }
#pragma unroll
            for (int i = 0; i < 16; i++) {
                float4 p4 = *(const float4*)(P + (wq * 16 + i) * 68 + kk);
                ull p0 = pk2(p4.x, p4.x), p1 = pk2(p4.y, p4.y);
                ull p2 = pk2(p4.z, p4.z), p3 = pk2(p4.w, p4.w);
                fma2(oacc[i][0], p0, v_[0][0]); fma2(oacc[i][1], p0, v_[0][1]);
                fma2(oacc[i][0], p1, v_[1][0]); fma2(oacc[i][1], p1, v_[1][1]);
                fma2(oacc[i][0], p2, v_[2][0]); fma2(oacc[i][1], p2, v_[2][1]);
                fma2(oacc[i][0], p3, v_[3][0]); fma2(oacc[i][1], p3, v_[3][1]);
            }
        }
    }

#pragma unroll
    for (int i = 0; i < 16; i++) {
        float2 a = upk2(oacc[i][0]);
        float2 c = upk2(oacc[i][1]);
        float* orow = outO + (size_t)(b * QQ + qb0 + wq * 16 + i) * EMBED + h * DH + dcol;
        *(float4*)orow = make_float4(a.x, a.y, c.x, c.y);
    }
}

// ---------------- launch ----------------
extern "C" void kernel_launch(void* const* d_in, const int* in_sizes, int n_in,
                              void* d_out, int out_size) {
    const float* query = (const float*)d_in[0];
    const float* key   = (const float*)d_in[1];
    const float* value = (const float*)d_in[2];
    const float* amask = (const float*)d_in[3];
    const float* qW = (const float*)d_in[4];
    const float* qb = (const float*)d_in[5];
    const float* kW = (const float*)d_in[6];
    const float* kb = (const float*)d_in[7];
    const float* vW = (const float*)d_in[8];
    const float* vb = (const float*)d_in[9];
    (void)in_sizes; (void)n_in; (void)out_size;

    float* outO = (float*)d_out;                             // [B,Q,EMBED]
    float* outW = outO + (size_t)BB * QQ * EMBED;            // [B,H,Q,K]

    float *pq, *pk_, *pv;
    cudaGetSymbolAddress((void**)&pq, g_q);
    cudaGetSymbolAddress((void**)&pk_, g_k);
    cudaGetSymbolAddress((void**)&pv, g_v);

    // HMMA projection GEMMs (split-bf16)
    {
        cudaFuncSetAttribute(gemm_mma,
                             cudaFuncAttributeMaxDynamicSharedMemorySize, GS_BYTES);
        dim3 gq(DOWN / 128, (BB * QQ) / 128);
        gemm_mma<<<gq, 256, GS_BYTES>>>(query, qW, qb, pq, BB * QQ, DOWN, DOWN);
        gemm_mma<<<gq, 256, GS_BYTES>>>(key, kW, kb, pk_, BB * KK, DOWN, DOWN);
        dim3 gv(EMBED / 128, (BB * KK) / 128);
        gemm_mma<<<gv, 256, GS_BYTES>>>(value, vW, vb, pv, BB * KK, EMBED, EMBED);
    }

    // fused attention
    {
        const int smem = (32768 + 4096 + 8704 + 8192 + 128) * 4; // 215,552 B
        cudaFuncSetAttribute(attn_kernel,
                             cudaFuncAttributeMaxDynamicSharedMemorySize, smem);
        dim3 ga(QQ / 128, HH, BB);
        attn_kernel<<<ga, 256, smem>>>(pq, pk_, pv, amask, outO, outW);
    }
}

// round 5
// speedup vs baseline: 2.7831x; 1.5815x over previous
#include <cuda_runtime.h>
#include <cuda_bf16.h>
#include <cstdint>

// Problem constants
#define BB   8
#define QQ   1024
#define KK   1024
#define EMBED 2048
#define DOWN  512
#define HH    16
#define DHD   32    // down head dim
#define DH    128   // value head dim

typedef unsigned long long ull;

// Scratch (device globals: allocation-free rule)
__device__ float g_q[BB * QQ * DOWN];     // 16 MB
__device__ float g_k[BB * KK * DOWN];     // 16 MB
__device__ float g_v[BB * KK * EMBED];    // 64 MB
__device__ float g_l[BB * HH * QQ];       // 512 KB (1/rowsum)

// ---------------- mma.sync helpers (non-'a' PTX, works on sm_103) ----------------
__device__ __forceinline__ uint32_t smem_u32(const void* p) {
    uint32_t a;
    asm("{ .reg .u64 t; cvta.to.shared.u64 t, %1; cvt.u32.u64 %0, t; }"
        : "=r"(a) : "l"(p));
    return a;
}
__device__ __forceinline__ void ldmx4(uint32_t* r, uint32_t addr) {
    asm volatile("ldmatrix.sync.aligned.m8n8.x4.shared.b16 {%0,%1,%2,%3}, [%4];"
                 : "=r"(r[0]), "=r"(r[1]), "=r"(r[2]), "=r"(r[3]) : "r"(addr));
}
__device__ __forceinline__ void ldmx4t(uint32_t* r, uint32_t addr) {
    asm volatile("ldmatrix.sync.aligned.m8n8.x4.trans.shared.b16 {%0,%1,%2,%3}, [%4];"
                 : "=r"(r[0]), "=r"(r[1]), "=r"(r[2]), "=r"(r[3]) : "r"(addr));
}
__device__ __forceinline__ void mma16816(float* d, const uint32_t* a, const uint32_t* b) {
    asm volatile(
        "mma.sync.aligned.m16n8k16.row.col.f32.bf16.bf16.f32 "
        "{%0,%1,%2,%3}, {%4,%5,%6,%7}, {%8,%9}, {%0,%1,%2,%3};"
        : "+f"(d[0]), "+f"(d[1]), "+f"(d[2]), "+f"(d[3])
        : "r"(a[0]), "r"(a[1]), "r"(a[2]), "r"(a[3]), "r"(b[0]), "r"(b[1]));
}
// pack two floats to bf16x2 (x0 -> low half / lower address)
__device__ __forceinline__ uint32_t bfpack(float x0, float x1) {
    uint32_t r;
    asm("cvt.rn.bf16x2.f32 %0, %1, %2;" : "=r"(r) : "f"(x1), "f"(x0));
    return r;
}
__device__ __forceinline__ float bftrunc(float x) {
    return __bfloat162float(__float2bfloat16_rn(x));
}

// ---------------- HMMA GEMM: C[M,N] = A[M,K] @ W[N,K]^T + bias ----------------
// (unchanged from round 4 — known-good)
#define GS_A_HI 0u
#define GS_A_LO 10240u
#define GS_B_HI 20480u
#define GS_B_LO 30720u
#define GS_BYTES 40960u

__global__ void __launch_bounds__(256, 2)
gemm_mma(const float* __restrict__ A, const float* __restrict__ W,
         const float* __restrict__ bias, float* __restrict__ C,
         int M, int N, int K) {
    extern __shared__ char smem[];
    const uint32_t sb = smem_u32(smem);
    const int tid = threadIdx.x;
    const int warp = tid >> 5, lane = tid & 31;
    const int wm = warp >> 2, wn = warp & 3;
    const int warp_row = wm * 64, warp_col = wn * 32;
    const int m0 = blockIdx.y * 128, n0 = blockIdx.x * 128;

    float acc[4][4][4];
#pragma unroll
    for (int i = 0; i < 4; i++)
#pragma unroll
        for (int j = 0; j < 4; j++)
#pragma unroll
            for (int t = 0; t < 4; t++) acc[i][j][t] = 0.f;

    const uint32_t a_lane_off = (uint32_t)((lane & 15) * 80 + (lane >> 4) * 16);
    const uint32_t b_lane_off = (uint32_t)(((lane >> 4) * 8 + (lane & 7)) * 80 + ((lane >> 3) & 1) * 16);

    for (int kt = 0; kt < K; kt += 32) {
        __syncthreads();
        const float* Ab = A + (size_t)m0 * K + kt;
        const float* Wb = W + (size_t)n0 * K + kt;
#pragma unroll
        for (int l = 0; l < 4; l++) {
            int i = tid + l * 256;
            int r = i >> 3, c4 = i & 7;
            uint32_t off = (uint32_t)(r * 80 + c4 * 8);

            float4 a4 = *(const float4*)(Ab + (size_t)r * K + c4 * 4);
            float hx = bftrunc(a4.x), hy = bftrunc(a4.y), hz = bftrunc(a4.z), hw = bftrunc(a4.w);
            *(uint2*)(smem + GS_A_HI + off) = make_uint2(bfpack(hx, hy), bfpack(hz, hw));
            *(uint2*)(smem + GS_A_LO + off) = make_uint2(bfpack(a4.x - hx, a4.y - hy),
                                                         bfpack(a4.z - hz, a4.w - hw));

            float4 w4 = *(const float4*)(Wb + (size_t)r * K + c4 * 4);
            hx = bftrunc(w4.x); hy = bftrunc(w4.y); hz = bftrunc(w4.z); hw = bftrunc(w4.w);
            *(uint2*)(smem + GS_B_HI + off) = make_uint2(bfpack(hx, hy), bfpack(hz, hw));
            *(uint2*)(smem + GS_B_LO + off) = make_uint2(bfpack(w4.x - hx, w4.y - hy),
                                                         bfpack(w4.z - hz, w4.w - hw));
        }
        __syncthreads();

#pragma unroll
        for (int kc = 0; kc < 2; kc++) {
            const uint32_t kco = (uint32_t)(kc * 32);
            uint32_t afrag[4][4], bfrag[2][4];
#pragma unroll
            for (int mt = 0; mt < 4; mt++)
                ldmx4(afrag[mt], sb + GS_A_HI + (uint32_t)((warp_row + mt * 16) * 80) + kco + a_lane_off);
#pragma unroll
            for (int np = 0; np < 2; np++)
                ldmx4(bfrag[np], sb + GS_B_HI + (uint32_t)((warp_col + np * 16) * 80) + kco + b_lane_off);
#pragma unroll
            for (int mt = 0; mt < 4; mt++)
#pragma unroll
                for (int nt = 0; nt < 4; nt++)
                    mma16816(acc[mt][nt], afrag[mt], &bfrag[nt >> 1][(nt & 1) * 2]);

#pragma unroll
            for (int mt = 0; mt < 4; mt++)
                ldmx4(afrag[mt], sb + GS_A_LO + (uint32_t)((warp_row + mt * 16) * 80) + kco + a_lane_off);
#pragma unroll
            for (int mt = 0; mt < 4; mt++)
#pragma unroll
                for (int nt = 0; nt < 4; nt++)
                    mma16816(acc[mt][nt], afrag[mt], &bfrag[nt >> 1][(nt & 1) * 2]);

#pragma unroll
            for (int mt = 0; mt < 4; mt++)
                ldmx4(afrag[mt], sb + GS_A_HI + (uint32_t)((warp_row + mt * 16) * 80) + kco + a_lane_off);
#pragma unroll
            for (int np = 0; np < 2; np++)
                ldmx4(bfrag[np], sb + GS_B_LO + (uint32_t)((warp_col + np * 16) * 80) + kco + b_lane_off);
#pragma unroll
            for (int mt = 0; mt < 4; mt++)
#pragma unroll
                for (int nt = 0; nt < 4; nt++)
                    mma16816(acc[mt][nt], afrag[mt], &bfrag[nt >> 1][(nt & 1) * 2]);
        }
    }

    const int lr = lane >> 2, lc = (lane & 3) * 2;
#pragma unroll
    for (int mt = 0; mt < 4; mt++) {
#pragma unroll
        for (int nt = 0; nt < 4; nt++) {
            int col = n0 + warp_col + nt * 8 + lc;
            float b0 = bias[col], b1 = bias[col + 1];
            int row0 = m0 + warp_row + mt * 16 + lr;
            *(float2*)(C + (size_t)row0 * N + col) =
                make_float2(acc[mt][nt][0] + b0, acc[mt][nt][1] + b1);
            *(float2*)(C + (size_t)(row0 + 8) * N + col) =
                make_float2(acc[mt][nt][2] + b0, acc[mt][nt][3] + b1);
        }
    }
}

// ---------------- mma attention: single pass ----------------
// grid (Q/128, H, B), 256 threads (8 warps, 2x4).
// Per chunk of 128 kpos: S = Q*K^T (split-bf16 x3) -> u = exp(logit) ->
// outW (unnormalized) + P smem (bf16 hi/lo) -> O += P @ V (split x3, ldmatrix.trans).
// Rowsums -> g_l (1/l); O scaled in epilogue; outW rescaled by scale_w kernel.
#define AS_QHI 0u
#define AS_QLO 10240u
#define AS_KHI 20480u
#define AS_KLO 30720u
#define AS_PHI 40960u
#define AS_PLO 75776u
#define AS_VHI 110592u
#define AS_VLO 145408u
#define AS_LRED 180224u           // 128*4 floats
#define AS_LINV 182272u           // 128 floats
#define AS_BYTES 182784u

__global__ void __launch_bounds__(256)
attn_mma(const float* __restrict__ qp, const float* __restrict__ kp,
         const float* __restrict__ vp, const float* __restrict__ mask,
         float* __restrict__ outO, float* __restrict__ outW,
         float* __restrict__ linv_g) {
    const int b = blockIdx.z, h = blockIdx.y;
    const int qb0 = blockIdx.x * 128;
    const int tid = threadIdx.x;
    const int warp = tid >> 5, lane = tid & 31;
    const int wm = warp >> 2, wn = warp & 3;
    const int warp_row = wm * 64;       // q rows
    const int warp_col = wn * 32;       // kpos (S) / d (PV)
    extern __shared__ char smem[];
    const uint32_t sb = smem_u32(smem);

    const int lr = lane >> 2, lc = (lane & 3) * 2;
    const uint32_t a80  = (uint32_t)((lane & 15) * 80 + (lane >> 4) * 16);
    const uint32_t b80  = (uint32_t)(((lane >> 4) * 8 + (lane & 7)) * 80 + ((lane >> 3) & 1) * 16);
    const uint32_t a272 = (uint32_t)((lane & 15) * 272 + (lane >> 4) * 16);
    const uint32_t v272 = (uint32_t)((lane & 15) * 272 + (lane >> 4) * 16);

    // ---- load + convert Q tile [128,32] ----
    {
        const float* qb_ = qp + (size_t)(b * QQ + qb0) * DOWN + h * DHD;
        for (int i = tid; i < 1024; i += 256) {
            int r = i >> 3, c4 = i & 7;
            uint32_t off = (uint32_t)(r * 80 + c4 * 8);
            float4 a4 = *(const float4*)(qb_ + (size_t)r * DOWN + c4 * 4);
            float hx = bftrunc(a4.x), hy = bftrunc(a4.y), hz = bftrunc(a4.z), hw = bftrunc(a4.w);
            *(uint2*)(smem + AS_QHI + off) = make_uint2(bfpack(hx, hy), bfpack(hz, hw));
            *(uint2*)(smem + AS_QLO + off) = make_uint2(bfpack(a4.x - hx, a4.y - hy),
                                                        bfpack(a4.z - hz, a4.w - hw));
        }
    }

    float oac[4][4][4];
#pragma unroll
    for (int i = 0; i < 4; i++)
#pragma unroll
        for (int j = 0; j < 4; j++)
#pragma unroll
            for (int t = 0; t < 4; t++) oac[i][j][t] = 0.f;
    float rs[4][2];
#pragma unroll
    for (int i = 0; i < 4; i++) { rs[i][0] = 0.f; rs[i][1] = 0.f; }

    const float scale = 0.1767766952966369f; // 1/sqrt(32)
    const float* mbase = mask + (size_t)b * QQ * KK + (size_t)qb0 * KK;
    float* wbase = outW + ((size_t)((b * HH + h) * QQ + qb0)) * KK;

    for (int cc = 0; cc < 8; cc++) {
        const int kb2 = cc * 128;
        __syncthreads();   // P/V/K from previous chunk consumed

        // ---- load + convert K chunk [128,32] and V chunk [128,128] ----
        {
            const float* kb_ = kp + (size_t)(b * KK + kb2) * DOWN + h * DHD;
            for (int i = tid; i < 1024; i += 256) {
                int r = i >> 3, c4 = i & 7;
                uint32_t off = (uint32_t)(r * 80 + c4 * 8);
                float4 a4 = *(const float4*)(kb_ + (size_t)r * DOWN + c4 * 4);
                float hx = bftrunc(a4.x), hy = bftrunc(a4.y), hz = bftrunc(a4.z), hw = bftrunc(a4.w);
                *(uint2*)(smem + AS_KHI + off) = make_uint2(bfpack(hx, hy), bfpack(hz, hw));
                *(uint2*)(smem + AS_KLO + off) = make_uint2(bfpack(a4.x - hx, a4.y - hy),
                                                            bfpack(a4.z - hz, a4.w - hw));
            }
            const float* vb_ = vp + (size_t)(b * KK + kb2) * EMBED + h * DH;
            for (int i = tid; i < 4096; i += 256) {
                int r = i >> 5, c4 = i & 31;
                uint32_t off = (uint32_t)(r * 272 + c4 * 8);
                float4 a4 = *(const float4*)(vb_ + (size_t)r * EMBED + c4 * 4);
                float hx = bftrunc(a4.x), hy = bftrunc(a4.y), hz = bftrunc(a4.z), hw = bftrunc(a4.w);
                *(uint2*)(smem + AS_VHI + off) = make_uint2(bfpack(hx, hy), bfpack(hz, hw));
                *(uint2*)(smem + AS_VLO + off) = make_uint2(bfpack(a4.x - hx, a4.y - hy),
                                                            bfpack(a4.z - hz, a4.w - hw));
            }
        }
        __syncthreads();

        // ---- S = Q*K^T (warp tile 64q x 32k) ----
        float sac[4][4][4];
#pragma unroll
        for (int i = 0; i < 4; i++)
#pragma unroll
            for (int j = 0; j < 4; j++)
#pragma unroll
                for (int t = 0; t < 4; t++) sac[i][j][t] = 0.f;

#pragma unroll
        for (int kc = 0; kc < 2; kc++) {
            const uint32_t kco = (uint32_t)(kc * 32);
            uint32_t afrag[4][4], bfrag[2][4];
#pragma unroll
            for (int mt = 0; mt < 4; mt++)
                ldmx4(afrag[mt], sb + AS_QHI + (uint32_t)((warp_row + mt * 16) * 80) + kco + a80);
#pragma unroll
            for (int np = 0; np < 2; np++)
                ldmx4(bfrag[np], sb + AS_KHI + (uint32_t)((warp_col + np * 16) * 80) + kco + b80);
#pragma unroll
            for (int mt = 0; mt < 4; mt++)
#pragma unroll
                for (int nt = 0; nt < 4; nt++)
                    mma16816(sac[mt][nt], afrag[mt], &bfrag[nt >> 1][(nt & 1) * 2]);
#pragma unroll
            for (int mt = 0; mt < 4; mt++)
                ldmx4(afrag[mt], sb + AS_QLO + (uint32_t)((warp_row + mt * 16) * 80) + kco + a80);
#pragma unroll
            for (int mt = 0; mt < 4; mt++)
#pragma unroll
                for (int nt = 0; nt < 4; nt++)
                    mma16816(sac[mt][nt], afrag[mt], &bfrag[nt >> 1][(nt & 1) * 2]);
#pragma unroll
            for (int mt = 0; mt < 4; mt++)
                ldmx4(afrag[mt], sb + AS_QHI + (uint32_t)((warp_row + mt * 16) * 80) + kco + a80);
#pragma unroll
            for (int np = 0; np < 2; np++)
                ldmx4(bfrag[np], sb + AS_KLO + (uint32_t)((warp_col + np * 16) * 80) + kco + b80);
#pragma unroll
            for (int mt = 0; mt < 4; mt++)
#pragma unroll
                for (int nt = 0; nt < 4; nt++)
                    mma16816(sac[mt][nt], afrag[mt], &bfrag[nt >> 1][(nt & 1) * 2]);
        }

        // ---- u = exp(scale*S + mask'), rowsum, store to outW + P smem ----
#pragma unroll
        for (int mt = 0; mt < 4; mt++) {
#pragma unroll
            for (int j = 0; j < 2; j++) {
                int row = warp_row + mt * 16 + lr + j * 8;
                const float* mrow = mbase + (size_t)row * KK + kb2;
                float* wrow = wbase + (size_t)row * KK + kb2;
                float rsl = 0.f;
#pragma unroll
                for (int nt = 0; nt < 4; nt++) {
                    int col = warp_col + nt * 8 + lc;
                    float2 mv = *(const float2*)(mrow + col);
                    float t0 = (mv.x == 0.f) ? -10000.f : mv.x;
                    float t1 = (mv.y == 0.f) ? -10000.f : mv.y;
                    float u0 = __expf(fmaf(sac[mt][nt][j * 2 + 0], scale, t0));
                    float u1 = __expf(fmaf(sac[mt][nt][j * 2 + 1], scale, t1));
                    rsl += u0 + u1;
                    *(float2*)(wrow + col) = make_float2(u0, u1);
                    float h0 = bftrunc(u0), h1 = bftrunc(u1);
                    uint32_t pb = (uint32_t)(row * 272 + col * 2);
                    *(uint32_t*)(smem + AS_PHI + pb) = bfpack(h0, h1);
                    *(uint32_t*)(smem + AS_PLO + pb) = bfpack(u0 - h0, u1 - h1);
                }
                rs[mt][j] += rsl;
            }
        }
        __syncthreads();

        // ---- O += P @ V (warp tile 64q x 32d, k=128) ----
#pragma unroll
        for (int kc = 0; kc < 8; kc++) {
            const uint32_t kco = (uint32_t)(kc * 32);           // A: k-offset bytes
            const uint32_t vrow = (uint32_t)(kc * 16 * 272);    // B: k-row offset
            uint32_t afrag[4][4], bfrag[2][4];
#pragma unroll
            for (int mt = 0; mt < 4; mt++)
                ldmx4(afrag[mt], sb + AS_PHI + (uint32_t)((warp_row + mt * 16) * 272) + kco + a272);
#pragma unroll
            for (int np = 0; np < 2; np++)
                ldmx4t(bfrag[np], sb + AS_VHI + vrow + (uint32_t)((warp_col + np * 16) * 2) + v272);
#pragma unroll
            for (int mt = 0; mt < 4; mt++)
#pragma unroll
                for (int nt = 0; nt < 4; nt++)
                    mma16816(oac[mt][nt], afrag[mt], &bfrag[nt >> 1][(nt & 1) * 2]);
#pragma unroll
            for (int mt = 0; mt < 4; mt++)
                ldmx4(afrag[mt], sb + AS_PLO + (uint32_t)((warp_row + mt * 16) * 272) + kco + a272);
#pragma unroll
            for (int mt = 0; mt < 4; mt++)
#pragma unroll
                for (int nt = 0; nt < 4; nt++)
                    mma16816(oac[mt][nt], afrag[mt], &bfrag[nt >> 1][(nt & 1) * 2]);
#pragma unroll
            for (int mt = 0; mt < 4; mt++)
                ldmx4(afrag[mt], sb + AS_PHI + (uint32_t)((warp_row + mt * 16) * 272) + kco + a272);
#pragma unroll
            for (int np = 0; np < 2; np++)
                ldmx4t(bfrag[np], sb + AS_VLO + vrow + (uint32_t)((warp_col + np * 16) * 2) + v272);
#pragma unroll
            for (int mt = 0; mt < 4; mt++)
#pragma unroll
                for (int nt = 0; nt < 4; nt++)
                    mma16816(oac[mt][nt], afrag[mt], &bfrag[nt >> 1][(nt & 1) * 2]);
        }
    }

    // ---- rowsum reduce -> linv ----
#pragma unroll
    for (int off = 1; off < 4; off <<= 1) {
#pragma unroll
        for (int mt = 0; mt < 4; mt++) {
            rs[mt][0] += __shfl_xor_sync(0xffffffffu, rs[mt][0], off);
            rs[mt][1] += __shfl_xor_sync(0xffffffffu, rs[mt][1], off);
        }
    }
    float* Lred = (float*)(smem + AS_LRED);
    float* Linv = (float*)(smem + AS_LINV);
    if ((lane & 3) == 0) {
#pragma unroll
        for (int mt = 0; mt < 4; mt++) {
#pragma unroll
            for (int j = 0; j < 2; j++) {
                int row = warp_row + mt * 16 + lr + j * 8;
                Lred[row * 4 + wn] = rs[mt][j];
            }
        }
    }
    __syncthreads();
    if (tid < 128) {
        float l = Lred[tid * 4] + Lred[tid * 4 + 1] + Lred[tid * 4 + 2] + Lred[tid * 4 + 3];
        float inv = 1.f / l;
        Linv[tid] = inv;
        linv_g[(size_t)(b * HH + h) * QQ + qb0 + tid] = inv;
    }
    __syncthreads();

    // ---- write O (normalized) ----
#pragma unroll
    for (int mt = 0; mt < 4; mt++) {
#pragma unroll
        for (int j = 0; j < 2; j++) {
            int row = warp_row + mt * 16 + lr + j * 8;
            float inv = Linv[row];
            float* orow = outO + (size_t)(b * QQ + qb0 + row) * EMBED + h * DH;
#pragma unroll
            for (int nt = 0; nt < 4; nt++) {
                int col = warp_col + nt * 8 + lc;
                *(float2*)(orow + col) = make_float2(oac[mt][nt][j * 2 + 0] * inv,
                                                     oac[mt][nt][j * 2 + 1] * inv);
            }
        }
    }
}

// ---------------- weight normalization ----------------
__global__ void __launch_bounds__(256)
scale_w(float* __restrict__ outW, const float* __restrict__ linv) {
    size_t idx = (size_t)blockIdx.x * 256 + threadIdx.x;   // one float4 each
    size_t row = idx >> 8;                                  // KK/4 = 256 float4/row
    float inv = __ldg(linv + row);
    float4 w = ((const float4*)outW)[idx];
    w.x *= inv; w.y *= inv; w.z *= inv; w.w *= inv;
    ((float4*)outW)[idx] = w;
}

// ---------------- launch ----------------
extern "C" void kernel_launch(void* const* d_in, const int* in_sizes, int n_in,
                              void* d_out, int out_size) {
    const float* query = (const float*)d_in[0];
    const float* key   = (const float*)d_in[1];
    const float* value = (const float*)d_in[2];
    const float* amask = (const float*)d_in[3];
    const float* qW = (const float*)d_in[4];
    const float* qb = (const float*)d_in[5];
    const float* kW = (const float*)d_in[6];
    const float* kb = (const float*)d_in[7];
    const float* vW = (const float*)d_in[8];
    const float* vb = (const float*)d_in[9];
    (void)in_sizes; (void)n_in; (void)out_size;

    float* outO = (float*)d_out;                             // [B,Q,EMBED]
    float* outW = outO + (size_t)BB * QQ * EMBED;            // [B,H,Q,K]

    float *pq, *pk_, *pv, *pl;
    cudaGetSymbolAddress((void**)&pq, g_q);
    cudaGetSymbolAddress((void**)&pk_, g_k);
    cudaGetSymbolAddress((void**)&pv, g_v);
    cudaGetSymbolAddress((void**)&pl, g_l);

    // HMMA projection GEMMs (split-bf16)
    {
        cudaFuncSetAttribute(gemm_mma,
                             cudaFuncAttributeMaxDynamicSharedMemorySize, GS_BYTES);
        dim3 gq(DOWN / 128, (BB * QQ) / 128);
        gemm_mma<<<gq, 256, GS_BYTES>>>(query, qW, qb, pq, BB * QQ, DOWN, DOWN);
        gemm_mma<<<gq, 256, GS_BYTES>>>(key, kW, kb, pk_, BB * KK, DOWN, DOWN);
        dim3 gv(EMBED / 128, (BB * KK) / 128);
        gemm_mma<<<gv, 256, GS_BYTES>>>(value, vW, vb, pv, BB * KK, EMBED, EMBED);
    }

    // mma attention (single pass) + weight normalization
    {
        cudaFuncSetAttribute(attn_mma,
                             cudaFuncAttributeMaxDynamicSharedMemorySize, AS_BYTES);
        dim3 ga(QQ / 128, HH, BB);
        attn_mma<<<ga, 256, AS_BYTES>>>(pq, pk_, pv, amask, outO, outW, pl);

        size_t nw4 = (size_t)BB * HH * QQ * KK / 4;          // 33.5M float4
        scale_w<<<(unsigned)(nw4 / 256), 256>>>(outW, pl);
    }
}